// round 13
// baseline (speedup 1.0000x reference)
#include <cuda_runtime.h>
#include <math.h>

// Scratch (allocation-free rule: __device__ globals)
__device__ float g_dct[128 * 3 * 64];    // dct branch input, (b,c,8,8)
__device__ float g_grad[128 * 3 * 64];   // grad branch input, (b,c,8,8)
__device__ float g_part[5][1024];        // partials: [s,D0,D1,G0,G1] x (b*8+grp)
__device__ unsigned int g_cnt[128];      // per-batch completion counters (self-resetting)

// ---------------------------------------------------------------------------
// Kernel 1: per (b,c) image: dct_in = A x A^T and sampled Sobel.
// A computed inline (Chebyshev recurrence). grid=384, block=256 (R5 core).
// ---------------------------------------------------------------------------
__global__ void __launch_bounds__(256) dct_grad_kernel(const float* __restrict__ x) {
    __shared__ float Rf2[8][25];
    __shared__ float As[256][8];       // As[m][o] = A[o][m]   (8 KB)
    __shared__ float Tp[4][8][256];    // team partials, later aliased as Ts (32 KB)

    const int tid = threadIdx.x;
    const int blk = blockIdx.x;
    const float* __restrict__ xc = x + (size_t)blk * 65536;

    if (tid < 200) {
        const int o = tid / 25, k = tid % 25;
        float sk = (k == 0) ? sqrtf(1.0f / 256.0f) : sqrtf(2.0f / 256.0f);
        float si = sqrtf(2.0f / 256.0f);
        float tw = (float)(2 * k + 1) * (1.0f / 512.0f);   // exact
        float c0 = cospif(tw * (float)(32 * o + 15));
        float c1 = cospif(tw * (float)(32 * o + 16));
        Rf2[o][k] = 0.5f * si * sk * (c0 + c1);
    }
    __syncthreads();
    {
        const float th = (float)(2 * tid + 1) * (1.0f / 512.0f);  // exact
        float cp = cospif(th);
        const float twoc = 2.0f * cp;
        float cpp = 1.0f;
        float a[8];
#pragma unroll
        for (int o = 0; o < 8; o++) a[o] = fmaf(Rf2[o][1], cp, Rf2[o][0]);
#pragma unroll
        for (int k = 2; k < 25; k++) {
            float ck = fmaf(twoc, cp, -cpp);
#pragma unroll
            for (int o = 0; o < 8; o++) a[o] = fmaf(Rf2[o][k], ck, a[o]);
            cpp = cp; cp = ck;
        }
#pragma unroll
        for (int o = 0; o < 8; o++) As[tid][o] = a[o];
    }
    __syncthreads();

    const int team = tid >> 6;
    const int t64  = tid & 63;

    float acc[8][4];
#pragma unroll
    for (int o = 0; o < 8; o++)
#pragma unroll
        for (int c = 0; c < 4; c++) acc[o][c] = 0.0f;

    const int mbase = team * 64;
#pragma unroll 4
    for (int mm = 0; mm < 64; mm++) {
        const int m = mbase + mm;
        float4 xv = reinterpret_cast<const float4*>(xc + (size_t)m * 256)[t64];
        float4 a0 = *reinterpret_cast<const float4*>(&As[m][0]);
        float4 a1 = *reinterpret_cast<const float4*>(&As[m][4]);
        acc[0][0] = fmaf(a0.x, xv.x, acc[0][0]);
        acc[0][1] = fmaf(a0.x, xv.y, acc[0][1]);
        acc[0][2] = fmaf(a0.x, xv.z, acc[0][2]);
        acc[0][3] = fmaf(a0.x, xv.w, acc[0][3]);
        acc[1][0] = fmaf(a0.y, xv.x, acc[1][0]);
        acc[1][1] = fmaf(a0.y, xv.y, acc[1][1]);
        acc[1][2] = fmaf(a0.y, xv.z, acc[1][2]);
        acc[1][3] = fmaf(a0.y, xv.w, acc[1][3]);
        acc[2][0] = fmaf(a0.z, xv.x, acc[2][0]);
        acc[2][1] = fmaf(a0.z, xv.y, acc[2][1]);
        acc[2][2] = fmaf(a0.z, xv.z, acc[2][2]);
        acc[2][3] = fmaf(a0.z, xv.w, acc[2][3]);
        acc[3][0] = fmaf(a0.w, xv.x, acc[3][0]);
        acc[3][1] = fmaf(a0.w, xv.y, acc[3][1]);
        acc[3][2] = fmaf(a0.w, xv.z, acc[3][2]);
        acc[3][3] = fmaf(a0.w, xv.w, acc[3][3]);
        acc[4][0] = fmaf(a1.x, xv.x, acc[4][0]);
        acc[4][1] = fmaf(a1.x, xv.y, acc[4][1]);
        acc[4][2] = fmaf(a1.x, xv.z, acc[4][2]);
        acc[4][3] = fmaf(a1.x, xv.w, acc[4][3]);
        acc[5][0] = fmaf(a1.y, xv.x, acc[5][0]);
        acc[5][1] = fmaf(a1.y, xv.y, acc[5][1]);
        acc[5][2] = fmaf(a1.y, xv.z, acc[5][2]);
        acc[5][3] = fmaf(a1.y, xv.w, acc[5][3]);
        acc[6][0] = fmaf(a1.z, xv.x, acc[6][0]);
        acc[6][1] = fmaf(a1.z, xv.y, acc[6][1]);
        acc[6][2] = fmaf(a1.z, xv.z, acc[6][2]);
        acc[6][3] = fmaf(a1.z, xv.w, acc[6][3]);
        acc[7][0] = fmaf(a1.w, xv.x, acc[7][0]);
        acc[7][1] = fmaf(a1.w, xv.y, acc[7][1]);
        acc[7][2] = fmaf(a1.w, xv.z, acc[7][2]);
        acc[7][3] = fmaf(a1.w, xv.w, acc[7][3]);
    }
#pragma unroll
    for (int o = 0; o < 8; o++)
        *reinterpret_cast<float4*>(&Tp[team][o][t64 * 4]) =
            make_float4(acc[o][0], acc[o][1], acc[o][2], acc[o][3]);
    __syncthreads();

    float* TsF = &Tp[0][0][0];   // Ts[o][c] = TsF[o*256 + c]
    {
        float s[8];
#pragma unroll
        for (int o = 0; o < 8; o++)
            s[o] = Tp[0][o][tid] + Tp[1][o][tid] + Tp[2][o][tid] + Tp[3][o][tid];
#pragma unroll
        for (int o = 0; o < 8; o++) TsF[o * 256 + tid] = s[o];
    }
    __syncthreads();

    if (tid < 64) {
        const int oy = tid >> 3, ox = tid & 7;
        const float* tsr = TsF + oy * 256;
        float s = 0.0f;
#pragma unroll 8
        for (int j = 0; j < 256; j++)
            s = fmaf(tsr[j], As[j][ox], s);
        g_dct[blk * 64 + tid] = s;
    } else if (tid < 128) {
        const int cl = tid - 64;
        const int r = 32 * (cl >> 3) + 15;
        const int c = 32 * (cl & 7) + 15;
        float p[4][4];
#pragma unroll
        for (int a = 0; a < 4; a++)
#pragma unroll
            for (int b = 0; b < 4; b++)
                p[a][b] = xc[(r - 1 + a) * 256 + (c - 1 + b)];
        float gsum = 0.0f;
#pragma unroll
        for (int i = 0; i < 2; i++)
#pragma unroll
            for (int j = 0; j < 2; j++) {
                float gx = (p[i][j + 2] - p[i][j])
                         + 2.0f * (p[i + 1][j + 2] - p[i + 1][j])
                         + (p[i + 2][j + 2] - p[i + 2][j]);
                float gy = (p[i + 2][j] - p[i][j])
                         + 2.0f * (p[i + 2][j + 1] - p[i][j + 1])
                         + (p[i + 2][j + 2] - p[i][j + 2]);
                gsum += sqrtf(gx * gx + gy * gy);
            }
        g_grad[blk * 64 + cl] = 0.25f * gsum;
    }
}

// ---------------------------------------------------------------------------
// Kernel 2: conv3x3 + BN + ReLU, register-blocked (4 cells/thread, 1 branch),
// + gate/classifier partials; LAST block per batch does the final combine.
// grid = 1024 (128 b x 8 groups), block = 256 = (br, lch, oy, xq).
// ---------------------------------------------------------------------------
__global__ void __launch_bounds__(256) head_kernel(
    const float* __restrict__ cw_d, const float* __restrict__ cb_d,
    const float* __restrict__ bg_d, const float* __restrict__ bb_d,
    const float* __restrict__ cw_g, const float* __restrict__ cb_g,
    const float* __restrict__ bg_g, const float* __restrict__ bb_g,
    const float* __restrict__ fw, const float* __restrict__ fb,
    const float* __restrict__ clsw, const float* __restrict__ clsb,
    float* __restrict__ out)
{
    __shared__ float tile[2][3][10][10];
    __shared__ float wsm[2][8][28];
    __shared__ float bnc[2][8][2];
    __shared__ float fws[8];
    __shared__ float wred[8][3];       // per warp: s, C0, C1
    __shared__ unsigned int s_last;

    const int bidx = blockIdx.x;
    const int b = bidx >> 3, grp = bidx & 7;
    const int tid = threadIdx.x;

    for (int t = tid; t < 432; t += 256) {
        int br_ = t / 216, r = t % 216;
        int lc = r / 27, i = r % 27;
        const float* w = br_ ? cw_g : cw_d;
        wsm[br_][lc][i] = w[(grp * 8 + lc) * 27 + i];
    }
    if (tid < 16) {
        int br_ = tid >> 3, lc = tid & 7, ch_ = grp * 8 + lc;
        const float rs = rsqrtf(1.0f + 1e-5f);
        float k = (br_ ? bg_g[ch_] : bg_d[ch_]) * rs;
        float bb = (br_ ? cb_g[ch_] : cb_d[ch_]) * k + (br_ ? bb_g[ch_] : bb_d[ch_]);
        bnc[br_][lc][0] = k; bnc[br_][lc][1] = bb;
    } else if (tid < 24) {
        fws[tid - 16] = fw[grp * 8 + (tid - 16)];
    }
    for (int t = tid; t < 600; t += 256) {
        int br_ = t / 300, rem = t % 300;
        int c = rem / 100, yy = (rem % 100) / 10, xx = rem % 10;
        float v = 0.0f;
        if (yy >= 1 && yy <= 8 && xx >= 1 && xx <= 8) {
            const float* src = br_ ? g_grad : g_dct;
            v = src[(b * 3 + c) * 64 + (yy - 1) * 8 + (xx - 1)];
        }
        tile[br_][c][yy][xx] = v;
    }
    __syncthreads();

    // thread = (br, lch, oy, xq): 4 cells (oy, 4xq..4xq+3), channel grp*8+lch
    const int br  = tid >> 7;
    const int lch = (tid >> 4) & 7;
    const int oy  = (tid >> 1) & 7;
    const int xq  = tid & 1;
    const int ch  = grp * 8 + lch;

    // weights + bn into registers (28 LDS total)
    float wr[27];
#pragma unroll
    for (int i = 0; i < 27; i++) wr[i] = wsm[br][lch][i];
    const float kbn = bnc[br][lch][0], bbn = bnc[br][lch][1];

    float acc[4] = {0.f, 0.f, 0.f, 0.f};
#pragma unroll
    for (int ci = 0; ci < 3; ci++) {
        float r0[6], r1[6], r2[6];
#pragma unroll
        for (int j = 0; j < 6; j++) {
            r0[j] = tile[br][ci][oy + 0][4 * xq + j];
            r1[j] = tile[br][ci][oy + 1][4 * xq + j];
            r2[j] = tile[br][ci][oy + 2][4 * xq + j];
        }
#pragma unroll
        for (int cx = 0; cx < 4; cx++) {
            float a = 0.f;
            a = fmaf(r0[cx + 0], wr[ci * 9 + 0], a);
            a = fmaf(r0[cx + 1], wr[ci * 9 + 1], a);
            a = fmaf(r0[cx + 2], wr[ci * 9 + 2], a);
            a = fmaf(r1[cx + 0], wr[ci * 9 + 3], a);
            a = fmaf(r1[cx + 1], wr[ci * 9 + 4], a);
            a = fmaf(r1[cx + 2], wr[ci * 9 + 5], a);
            a = fmaf(r2[cx + 0], wr[ci * 9 + 6], a);
            a = fmaf(r2[cx + 1], wr[ci * 9 + 7], a);
            a = fmaf(r2[cx + 2], wr[ci * 9 + 8], a);
            acc[cx] += a;
        }
    }

    float v0 = fmaxf(fmaf(acc[0], kbn, bbn), 0.f);
    float v1 = fmaxf(fmaf(acc[1], kbn, bbn), 0.f);
    float v2 = fmaxf(fmaf(acc[2], kbn, bbn), 0.f);
    float v3 = fmaxf(fmaf(acc[3], kbn, bbn), 0.f);

    float s_acc = (v0 + v1 + v2 + v3) * fws[lch];

    // classifier partials: flat base = ch*64 + oy*8 + 4*xq (float4-aligned)
    const int f4 = ch * 16 + oy * 2 + xq;
    float4 w0 = reinterpret_cast<const float4*>(clsw)[f4];
    float4 w1 = reinterpret_cast<const float4*>(clsw + 4096)[f4];
    float C0 = v0 * w0.x + v1 * w0.y + v2 * w0.z + v3 * w0.w;
    float C1 = v0 * w1.x + v1 * w1.y + v2 * w1.z + v3 * w1.w;

    // warp is branch-pure (warp = 2 lch x 8 oy x 2 xq, same br)
#pragma unroll
    for (int off = 16; off > 0; off >>= 1) {
        s_acc += __shfl_down_sync(0xffffffffu, s_acc, off);
        C0 += __shfl_down_sync(0xffffffffu, C0, off);
        C1 += __shfl_down_sync(0xffffffffu, C1, off);
    }
    if ((tid & 31) == 0) {
        int w = tid >> 5;
        wred[w][0] = s_acc; wred[w][1] = C0; wred[w][2] = C1;
    }
    __syncthreads();

    if (tid < 5) {
        // fixed-order combine: warps 0-3 = dct branch, 4-7 = grad branch
        float s;
        if (tid == 0)       s = (wred[0][0] + wred[1][0] + wred[2][0] + wred[3][0])
                              + (wred[4][0] + wred[5][0] + wred[6][0] + wred[7][0]);
        else if (tid == 1)  s = wred[0][1] + wred[1][1] + wred[2][1] + wred[3][1];  // D0
        else if (tid == 2)  s = wred[0][2] + wred[1][2] + wred[2][2] + wred[3][2];  // D1
        else if (tid == 3)  s = wred[4][1] + wred[5][1] + wred[6][1] + wred[7][1];  // G0
        else                s = wred[4][2] + wred[5][2] + wred[6][2] + wred[7][2];  // G1
        g_part[tid][bidx] = s;
    }
    __syncthreads();
    if (tid == 0) {
        __threadfence();
        unsigned int old = atomicAdd(&g_cnt[b], 1u);
        s_last = (old == 7u) ? 1u : 0u;
    }
    __syncthreads();

    if (s_last && tid < 32) {
        float v[5] = {0.f, 0.f, 0.f, 0.f, 0.f};
        if (tid < 8) {
#pragma unroll
            for (int j = 0; j < 5; j++) v[j] = __ldcg(&g_part[j][b * 8 + tid]);
        }
#pragma unroll
        for (int j = 0; j < 5; j++) {
            v[j] += __shfl_xor_sync(0xffffffffu, v[j], 1);
            v[j] += __shfl_xor_sync(0xffffffffu, v[j], 2);
            v[j] += __shfl_xor_sync(0xffffffffu, v[j], 4);
        }
        if (tid == 0) {
            float w = 1.0f / (1.0f + expf(-(v[0] * (1.0f / 64.0f) + fb[0])));
            out[b * 2 + 0] = w * v[1] + (1.0f - w) * v[3] + clsb[0];
            out[b * 2 + 1] = w * v[2] + (1.0f - w) * v[4] + clsb[1];
            g_cnt[b] = 0u;   // reset for next graph replay
        }
    }
}

// ---------------------------------------------------------------------------
extern "C" void kernel_launch(void* const* d_in, const int* in_sizes, int n_in,
                              void* d_out, int out_size) {
    const float* x     = (const float*)d_in[0];
    const float* cw_d  = (const float*)d_in[1];
    const float* cb_d  = (const float*)d_in[2];
    const float* bg_d  = (const float*)d_in[3];
    const float* bb_d  = (const float*)d_in[4];
    const float* cw_g  = (const float*)d_in[5];
    const float* cb_g  = (const float*)d_in[6];
    const float* bg_g  = (const float*)d_in[7];
    const float* bb_g  = (const float*)d_in[8];
    const float* fw    = (const float*)d_in[9];
    const float* fb    = (const float*)d_in[10];
    const float* clsw  = (const float*)d_in[11];
    const float* clsb  = (const float*)d_in[12];
    float* out = (float*)d_out;

    dct_grad_kernel<<<384, 256>>>(x);
    head_kernel<<<1024, 256>>>(cw_d, cb_d, bg_d, bb_d,
                               cw_g, cb_g, bg_g, bb_g,
                               fw, fb, clsw, clsb, out);
}

// round 14
// speedup vs baseline: 1.3533x; 1.3533x over previous
#include <cuda_runtime.h>
#include <math.h>

// Scratch (allocation-free rule: __device__ globals)
__device__ float g_dct[128 * 3 * 64];    // dct branch input, (b,c,8,8)
__device__ float g_grad[128 * 3 * 64];   // grad branch input, (b,c,8,8)

// ---------------------------------------------------------------------------
// Kernel 1: per (b,c) image: dct_in = A x A^T and sampled Sobel.
// A computed inline (Chebyshev recurrence). grid=384, block=256 (R5 core).
// ---------------------------------------------------------------------------
__global__ void __launch_bounds__(256) dct_grad_kernel(const float* __restrict__ x) {
    __shared__ float Rf2[8][25];
    __shared__ float As[256][8];       // As[m][o] = A[o][m]   (8 KB)
    __shared__ float Tp[4][8][256];    // team partials, later aliased as Ts (32 KB)

    const int tid = threadIdx.x;
    const int blk = blockIdx.x;
    const float* __restrict__ xc = x + (size_t)blk * 65536;

    if (tid < 200) {
        const int o = tid / 25, k = tid % 25;
        float sk = (k == 0) ? sqrtf(1.0f / 256.0f) : sqrtf(2.0f / 256.0f);
        float si = sqrtf(2.0f / 256.0f);
        float tw = (float)(2 * k + 1) * (1.0f / 512.0f);   // exact
        float c0 = cospif(tw * (float)(32 * o + 15));
        float c1 = cospif(tw * (float)(32 * o + 16));
        Rf2[o][k] = 0.5f * si * sk * (c0 + c1);
    }
    __syncthreads();
    {
        const float th = (float)(2 * tid + 1) * (1.0f / 512.0f);  // exact
        float cp = cospif(th);
        const float twoc = 2.0f * cp;
        float cpp = 1.0f;
        float a[8];
#pragma unroll
        for (int o = 0; o < 8; o++) a[o] = fmaf(Rf2[o][1], cp, Rf2[o][0]);
#pragma unroll
        for (int k = 2; k < 25; k++) {
            float ck = fmaf(twoc, cp, -cpp);
#pragma unroll
            for (int o = 0; o < 8; o++) a[o] = fmaf(Rf2[o][k], ck, a[o]);
            cpp = cp; cp = ck;
        }
#pragma unroll
        for (int o = 0; o < 8; o++) As[tid][o] = a[o];
    }
    __syncthreads();

    const int team = tid >> 6;
    const int t64  = tid & 63;

    float acc[8][4];
#pragma unroll
    for (int o = 0; o < 8; o++)
#pragma unroll
        for (int c = 0; c < 4; c++) acc[o][c] = 0.0f;

    const int mbase = team * 64;
#pragma unroll 4
    for (int mm = 0; mm < 64; mm++) {
        const int m = mbase + mm;
        float4 xv = reinterpret_cast<const float4*>(xc + (size_t)m * 256)[t64];
        float4 a0 = *reinterpret_cast<const float4*>(&As[m][0]);
        float4 a1 = *reinterpret_cast<const float4*>(&As[m][4]);
        acc[0][0] = fmaf(a0.x, xv.x, acc[0][0]);
        acc[0][1] = fmaf(a0.x, xv.y, acc[0][1]);
        acc[0][2] = fmaf(a0.x, xv.z, acc[0][2]);
        acc[0][3] = fmaf(a0.x, xv.w, acc[0][3]);
        acc[1][0] = fmaf(a0.y, xv.x, acc[1][0]);
        acc[1][1] = fmaf(a0.y, xv.y, acc[1][1]);
        acc[1][2] = fmaf(a0.y, xv.z, acc[1][2]);
        acc[1][3] = fmaf(a0.y, xv.w, acc[1][3]);
        acc[2][0] = fmaf(a0.z, xv.x, acc[2][0]);
        acc[2][1] = fmaf(a0.z, xv.y, acc[2][1]);
        acc[2][2] = fmaf(a0.z, xv.z, acc[2][2]);
        acc[2][3] = fmaf(a0.z, xv.w, acc[2][3]);
        acc[3][0] = fmaf(a0.w, xv.x, acc[3][0]);
        acc[3][1] = fmaf(a0.w, xv.y, acc[3][1]);
        acc[3][2] = fmaf(a0.w, xv.z, acc[3][2]);
        acc[3][3] = fmaf(a0.w, xv.w, acc[3][3]);
        acc[4][0] = fmaf(a1.x, xv.x, acc[4][0]);
        acc[4][1] = fmaf(a1.x, xv.y, acc[4][1]);
        acc[4][2] = fmaf(a1.x, xv.z, acc[4][2]);
        acc[4][3] = fmaf(a1.x, xv.w, acc[4][3]);
        acc[5][0] = fmaf(a1.y, xv.x, acc[5][0]);
        acc[5][1] = fmaf(a1.y, xv.y, acc[5][1]);
        acc[5][2] = fmaf(a1.y, xv.z, acc[5][2]);
        acc[5][3] = fmaf(a1.y, xv.w, acc[5][3]);
        acc[6][0] = fmaf(a1.z, xv.x, acc[6][0]);
        acc[6][1] = fmaf(a1.z, xv.y, acc[6][1]);
        acc[6][2] = fmaf(a1.z, xv.z, acc[6][2]);
        acc[6][3] = fmaf(a1.z, xv.w, acc[6][3]);
        acc[7][0] = fmaf(a1.w, xv.x, acc[7][0]);
        acc[7][1] = fmaf(a1.w, xv.y, acc[7][1]);
        acc[7][2] = fmaf(a1.w, xv.z, acc[7][2]);
        acc[7][3] = fmaf(a1.w, xv.w, acc[7][3]);
    }
#pragma unroll
    for (int o = 0; o < 8; o++)
        *reinterpret_cast<float4*>(&Tp[team][o][t64 * 4]) =
            make_float4(acc[o][0], acc[o][1], acc[o][2], acc[o][3]);
    __syncthreads();

    float* TsF = &Tp[0][0][0];   // Ts[o][c] = TsF[o*256 + c]
    {
        float s[8];
#pragma unroll
        for (int o = 0; o < 8; o++)
            s[o] = Tp[0][o][tid] + Tp[1][o][tid] + Tp[2][o][tid] + Tp[3][o][tid];
#pragma unroll
        for (int o = 0; o < 8; o++) TsF[o * 256 + tid] = s[o];
    }
    __syncthreads();

    if (tid < 64) {
        const int oy = tid >> 3, ox = tid & 7;
        const float* tsr = TsF + oy * 256;
        float s = 0.0f;
#pragma unroll 8
        for (int j = 0; j < 256; j++)
            s = fmaf(tsr[j], As[j][ox], s);
        g_dct[blk * 64 + tid] = s;
    } else if (tid < 128) {
        const int cl = tid - 64;
        const int r = 32 * (cl >> 3) + 15;
        const int c = 32 * (cl & 7) + 15;
        float p[4][4];
#pragma unroll
        for (int a = 0; a < 4; a++)
#pragma unroll
            for (int b = 0; b < 4; b++)
                p[a][b] = xc[(r - 1 + a) * 256 + (c - 1 + b)];
        float gsum = 0.0f;
#pragma unroll
        for (int i = 0; i < 2; i++)
#pragma unroll
            for (int j = 0; j < 2; j++) {
                float gx = (p[i][j + 2] - p[i][j])
                         + 2.0f * (p[i + 1][j + 2] - p[i + 1][j])
                         + (p[i + 2][j + 2] - p[i + 2][j]);
                float gy = (p[i + 2][j] - p[i][j])
                         + 2.0f * (p[i + 2][j + 1] - p[i][j + 1])
                         + (p[i + 2][j + 2] - p[i][j + 2]);
                gsum += sqrtf(gx * gx + gy * gy);
            }
        g_grad[blk * 64 + cl] = 0.25f * gsum;
    }
}

// ---------------------------------------------------------------------------
// Kernel 2 (R7 head, verbatim): conv3x3 + BN + ReLU both branches, gate,
// classifier, output. grid = 128 (one block per batch), block = 512.
// ---------------------------------------------------------------------------
__global__ void __launch_bounds__(512) head_kernel(
    const float* __restrict__ cw_d, const float* __restrict__ cb_d,
    const float* __restrict__ bg_d, const float* __restrict__ bb_d,
    const float* __restrict__ cw_g, const float* __restrict__ cb_g,
    const float* __restrict__ bg_g, const float* __restrict__ bb_g,
    const float* __restrict__ fw, const float* __restrict__ fb,
    const float* __restrict__ clsw, const float* __restrict__ clsb,
    float* __restrict__ out)
{
    __shared__ float tile[2][3][10][10];   // zero-padded inputs
    __shared__ float wsm[2][64][28];       // conv weights, padded 27->28 (14 KB)
    __shared__ float red[512];
    __shared__ float warpred[16][4];
    __shared__ float sfw[64];

    const int b = blockIdx.x;
    const int tid = threadIdx.x;

    for (int t = tid; t < 64 * 27; t += 512) {
        int co_ = t / 27, i_ = t % 27;
        wsm[0][co_][i_] = cw_d[t];
        wsm[1][co_][i_] = cw_g[t];
    }
    for (int t = tid; t < 600; t += 512) {
        int br = t / 300, rem = t % 300;
        int c = rem / 100, yy = (rem % 100) / 10, xx = rem % 10;
        float v = 0.0f;
        if (yy >= 1 && yy <= 8 && xx >= 1 && xx <= 8) {
            const float* src = br ? g_grad : g_dct;
            v = src[(b * 3 + c) * 64 + (yy - 1) * 8 + (xx - 1)];
        }
        tile[br][c][yy][xx] = v;
    }
    __syncthreads();

    const int co = tid >> 3;   // 0..63  output channel
    const int oy = tid & 7;    // 0..7   output row (8 cells along x)

    const float rs = rsqrtf(1.0f + 1e-5f);
    const float kd  = bg_d[co] * rs;
    const float bd  = cb_d[co] * kd + bb_d[co];
    const float kg  = bg_g[co] * rs;
    const float bgc = cb_g[co] * kg + bb_g[co];

    float dv[8], gv[8];
    {
        const float* wr = &wsm[0][co][0];
#pragma unroll
        for (int i = 0; i < 8; i++) {
            float a = 0.0f;
#pragma unroll
            for (int ci = 0; ci < 3; ci++)
#pragma unroll
                for (int ky = 0; ky < 3; ky++)
#pragma unroll
                    for (int kx = 0; kx < 3; kx++)
                        a = fmaf(tile[0][ci][oy + ky][i + kx], wr[ci * 9 + ky * 3 + kx], a);
            dv[i] = fmaxf(fmaf(a, kd, bd), 0.0f);
        }
    }
    {
        const float* wr = &wsm[1][co][0];
#pragma unroll
        for (int i = 0; i < 8; i++) {
            float a = 0.0f;
#pragma unroll
            for (int ci = 0; ci < 3; ci++)
#pragma unroll
                for (int ky = 0; ky < 3; ky++)
#pragma unroll
                    for (int kx = 0; kx < 3; kx++)
                        a = fmaf(tile[1][ci][oy + ky][i + kx], wr[ci * 9 + ky * 3 + kx], a);
            gv[i] = fmaxf(fmaf(a, kg, bgc), 0.0f);
        }
    }

    // gate partial
    float psum = 0.0f;
#pragma unroll
    for (int i = 0; i < 8; i++) psum += dv[i] + gv[i];
    red[tid] = psum;

    // classifier partials: flat = co*64 + oy*8 + i = tid*8 + i  (float4 loads)
    float aD0, aD1, aG0, aG1;
    {
        const float4* __restrict__ c0 = reinterpret_cast<const float4*>(clsw) + tid * 2;
        const float4* __restrict__ c1 = reinterpret_cast<const float4*>(clsw + 4096) + tid * 2;
        float4 w00 = c0[0], w01 = c0[1];
        float4 w10 = c1[0], w11 = c1[1];
        aD0 = dv[0]*w00.x + dv[1]*w00.y + dv[2]*w00.z + dv[3]*w00.w
            + dv[4]*w01.x + dv[5]*w01.y + dv[6]*w01.z + dv[7]*w01.w;
        aD1 = dv[0]*w10.x + dv[1]*w10.y + dv[2]*w10.z + dv[3]*w10.w
            + dv[4]*w11.x + dv[5]*w11.y + dv[6]*w11.z + dv[7]*w11.w;
        aG0 = gv[0]*w00.x + gv[1]*w00.y + gv[2]*w00.z + gv[3]*w00.w
            + gv[4]*w01.x + gv[5]*w01.y + gv[6]*w01.z + gv[7]*w01.w;
        aG1 = gv[0]*w10.x + gv[1]*w10.y + gv[2]*w10.z + gv[3]*w10.w
            + gv[4]*w11.x + gv[5]*w11.y + gv[6]*w11.z + gv[7]*w11.w;
    }
#pragma unroll
    for (int off = 16; off > 0; off >>= 1) {
        aD0 += __shfl_down_sync(0xffffffffu, aD0, off);
        aD1 += __shfl_down_sync(0xffffffffu, aD1, off);
        aG0 += __shfl_down_sync(0xffffffffu, aG0, off);
        aG1 += __shfl_down_sync(0xffffffffu, aG1, off);
    }
    if ((tid & 31) == 0) {
        warpred[tid >> 5][0] = aD0;
        warpred[tid >> 5][1] = aD1;
        warpred[tid >> 5][2] = aG0;
        warpred[tid >> 5][3] = aG1;
    }
    __syncthreads();

    if (tid < 64) {
        float s = 0.0f;
#pragma unroll
        for (int k = 0; k < 8; k++) s += red[tid * 8 + k];
        sfw[tid] = (s * (1.0f / 64.0f)) * fw[tid];
    }
    __syncthreads();

    if (tid == 0) {
        float tot = fb[0];
#pragma unroll
        for (int c2 = 0; c2 < 64; c2++) tot += sfw[c2];
        float w = 1.0f / (1.0f + expf(-tot));
        float D0 = 0.f, D1 = 0.f, G0 = 0.f, G1 = 0.f;
#pragma unroll
        for (int wd = 0; wd < 16; wd++) {
            D0 += warpred[wd][0];
            D1 += warpred[wd][1];
            G0 += warpred[wd][2];
            G1 += warpred[wd][3];
        }
        out[b * 2 + 0] = w * D0 + (1.0f - w) * G0 + clsb[0];
        out[b * 2 + 1] = w * D1 + (1.0f - w) * G1 + clsb[1];
    }
}

// ---------------------------------------------------------------------------
extern "C" void kernel_launch(void* const* d_in, const int* in_sizes, int n_in,
                              void* d_out, int out_size) {
    const float* x     = (const float*)d_in[0];
    const float* cw_d  = (const float*)d_in[1];
    const float* cb_d  = (const float*)d_in[2];
    const float* bg_d  = (const float*)d_in[3];
    const float* bb_d  = (const float*)d_in[4];
    const float* cw_g  = (const float*)d_in[5];
    const float* cb_g  = (const float*)d_in[6];
    const float* bg_g  = (const float*)d_in[7];
    const float* bb_g  = (const float*)d_in[8];
    const float* fw    = (const float*)d_in[9];
    const float* fb    = (const float*)d_in[10];
    const float* clsw  = (const float*)d_in[11];
    const float* clsb  = (const float*)d_in[12];
    float* out = (float*)d_out;

    dct_grad_kernel<<<384, 256>>>(x);
    head_kernel<<<128, 512>>>(cw_d, cb_d, bg_d, bb_d,
                              cw_g, cb_g, bg_g, bb_g,
                              fw, fb, clsw, clsb, out);
}

// round 15
// speedup vs baseline: 1.7094x; 1.2632x over previous
#include <cuda_runtime.h>
#include <math.h>

// Scratch (allocation-free rule: __device__ globals)
__device__ float g_A[8 * 256];          // combined DCT-mask-iDCT-resize operator
__device__ float g_dct[128 * 3 * 64];   // dct branch input, (b,c,8,8)
__device__ float g_grad[128 * 3 * 64];  // grad branch input, (b,c,8,8)

// ---------------------------------------------------------------------------
// Setup (R5 form): Chebyshev recurrence, 1 cospif + FMA chain. grid=8, block=256
// ---------------------------------------------------------------------------
__global__ void setupA_kernel() {
    __shared__ float Rf[32];
    const int o = blockIdx.x;
    const int j = threadIdx.x;
    const float r0 = (float)(32 * o + 15), r1 = (float)(32 * o + 16);
    if (j < 25) {
        float sk = (j == 0) ? sqrtf(1.0f / 256.0f) : sqrtf(2.0f / 256.0f);
        float si = sqrtf(2.0f / 256.0f);
        float tw = (float)(2 * j + 1) * (1.0f / 512.0f);   // exact
        float c0 = cospif(tw * r0);
        float c1 = cospif(tw * r1);
        Rf[j] = 0.5f * si * sk * (c0 + c1);
    }
    __syncthreads();
    const float th = (float)(2 * j + 1) * (1.0f / 512.0f);  // exact
    float cp = cospif(th);
    const float twoc = 2.0f * cp;
    float cpp = 1.0f;
    float a = fmaf(Rf[1], cp, Rf[0]);
#pragma unroll
    for (int k = 2; k < 25; k++) {
        float ck = fmaf(twoc, cp, -cpp);
        a = fmaf(Rf[k], ck, a);
        cpp = cp; cp = ck;
    }
    g_A[o * 256 + j] = a;
}

// ---------------------------------------------------------------------------
// Kernel 1 (R5 core + explicit MLP-8 load batching in pass 1).
// grid = 384, block = 256 (4 teams x 64 threads)
// ---------------------------------------------------------------------------
__global__ void __launch_bounds__(256) dct_grad_kernel(const float* __restrict__ x) {
    __shared__ float As[256][8];       // As[m][o] = A[o][m]   (8 KB)
    __shared__ float Tp[4][8][256];    // team partials, later aliased as Ts (32 KB)

    const int tid = threadIdx.x;
    const int blk = blockIdx.x;
    const float* __restrict__ xc = x + (size_t)blk * 65536;

#pragma unroll
    for (int o = 0; o < 8; o++) As[tid][o] = g_A[o * 256 + tid];
    __syncthreads();

    const int team = tid >> 6;         // rows 64*team .. 64*team+63
    const int t64  = tid & 63;         // columns 4*t64 .. 4*t64+3

    float acc[8][4];
#pragma unroll
    for (int o = 0; o < 8; o++)
#pragma unroll
        for (int c = 0; c < 4; c++) acc[o][c] = 0.0f;

    const float4* __restrict__ xrow = reinterpret_cast<const float4*>(xc) + t64;
    const int mbase = team * 64;

#pragma unroll
    for (int chunk = 0; chunk < 8; chunk++) {
        // batch 8 LDG.128 back-to-back -> MLP 8 per thread
        float4 xv[8];
#pragma unroll
        for (int u = 0; u < 8; u++)
            xv[u] = xrow[(size_t)(mbase + chunk * 8 + u) * 64];
#pragma unroll
        for (int u = 0; u < 8; u++) {
            const int m = mbase + chunk * 8 + u;
            float4 a0 = *reinterpret_cast<const float4*>(&As[m][0]);
            float4 a1 = *reinterpret_cast<const float4*>(&As[m][4]);
            acc[0][0] = fmaf(a0.x, xv[u].x, acc[0][0]);
            acc[0][1] = fmaf(a0.x, xv[u].y, acc[0][1]);
            acc[0][2] = fmaf(a0.x, xv[u].z, acc[0][2]);
            acc[0][3] = fmaf(a0.x, xv[u].w, acc[0][3]);
            acc[1][0] = fmaf(a0.y, xv[u].x, acc[1][0]);
            acc[1][1] = fmaf(a0.y, xv[u].y, acc[1][1]);
            acc[1][2] = fmaf(a0.y, xv[u].z, acc[1][2]);
            acc[1][3] = fmaf(a0.y, xv[u].w, acc[1][3]);
            acc[2][0] = fmaf(a0.z, xv[u].x, acc[2][0]);
            acc[2][1] = fmaf(a0.z, xv[u].y, acc[2][1]);
            acc[2][2] = fmaf(a0.z, xv[u].z, acc[2][2]);
            acc[2][3] = fmaf(a0.z, xv[u].w, acc[2][3]);
            acc[3][0] = fmaf(a0.w, xv[u].x, acc[3][0]);
            acc[3][1] = fmaf(a0.w, xv[u].y, acc[3][1]);
            acc[3][2] = fmaf(a0.w, xv[u].z, acc[3][2]);
            acc[3][3] = fmaf(a0.w, xv[u].w, acc[3][3]);
            acc[4][0] = fmaf(a1.x, xv[u].x, acc[4][0]);
            acc[4][1] = fmaf(a1.x, xv[u].y, acc[4][1]);
            acc[4][2] = fmaf(a1.x, xv[u].z, acc[4][2]);
            acc[4][3] = fmaf(a1.x, xv[u].w, acc[4][3]);
            acc[5][0] = fmaf(a1.y, xv[u].x, acc[5][0]);
            acc[5][1] = fmaf(a1.y, xv[u].y, acc[5][1]);
            acc[5][2] = fmaf(a1.y, xv[u].z, acc[5][2]);
            acc[5][3] = fmaf(a1.y, xv[u].w, acc[5][3]);
            acc[6][0] = fmaf(a1.z, xv[u].x, acc[6][0]);
            acc[6][1] = fmaf(a1.z, xv[u].y, acc[6][1]);
            acc[6][2] = fmaf(a1.z, xv[u].z, acc[6][2]);
            acc[6][3] = fmaf(a1.z, xv[u].w, acc[6][3]);
            acc[7][0] = fmaf(a1.w, xv[u].x, acc[7][0]);
            acc[7][1] = fmaf(a1.w, xv[u].y, acc[7][1]);
            acc[7][2] = fmaf(a1.w, xv[u].z, acc[7][2]);
            acc[7][3] = fmaf(a1.w, xv[u].w, acc[7][3]);
        }
    }
#pragma unroll
    for (int o = 0; o < 8; o++)
        *reinterpret_cast<float4*>(&Tp[team][o][t64 * 4]) =
            make_float4(acc[o][0], acc[o][1], acc[o][2], acc[o][3]);
    __syncthreads();

    float* TsF = &Tp[0][0][0];   // Ts[o][c] = TsF[o*256 + c]
    {
        float s[8];
#pragma unroll
        for (int o = 0; o < 8; o++)
            s[o] = Tp[0][o][tid] + Tp[1][o][tid] + Tp[2][o][tid] + Tp[3][o][tid];
#pragma unroll
        for (int o = 0; o < 8; o++) TsF[o * 256 + tid] = s[o];
    }
    __syncthreads();

    if (tid < 64) {
        const int oy = tid >> 3, ox = tid & 7;
        const float* tsr = TsF + oy * 256;
        float s = 0.0f;
#pragma unroll 8
        for (int j = 0; j < 256; j++)
            s = fmaf(tsr[j], As[j][ox], s);
        g_dct[blk * 64 + tid] = s;
    } else if (tid < 128) {
        const int cl = tid - 64;
        const int r = 32 * (cl >> 3) + 15;
        const int c = 32 * (cl & 7) + 15;
        float p[4][4];
#pragma unroll
        for (int a = 0; a < 4; a++)
#pragma unroll
            for (int b = 0; b < 4; b++)
                p[a][b] = xc[(r - 1 + a) * 256 + (c - 1 + b)];
        float gsum = 0.0f;
#pragma unroll
        for (int i = 0; i < 2; i++)
#pragma unroll
            for (int j = 0; j < 2; j++) {
                float gx = (p[i][j + 2] - p[i][j])
                         + 2.0f * (p[i + 1][j + 2] - p[i + 1][j])
                         + (p[i + 2][j + 2] - p[i + 2][j]);
                float gy = (p[i + 2][j] - p[i][j])
                         + 2.0f * (p[i + 2][j + 1] - p[i][j + 1])
                         + (p[i + 2][j + 2] - p[i][j + 2]);
                gsum += sqrtf(gx * gx + gy * gy);
            }
        g_grad[blk * 64 + cl] = 0.25f * gsum;
    }
}

// ---------------------------------------------------------------------------
// Kernel 2 (R7 head, verbatim): grid = 128, block = 512.
// ---------------------------------------------------------------------------
__global__ void __launch_bounds__(512) head_kernel(
    const float* __restrict__ cw_d, const float* __restrict__ cb_d,
    const float* __restrict__ bg_d, const float* __restrict__ bb_d,
    const float* __restrict__ cw_g, const float* __restrict__ cb_g,
    const float* __restrict__ bg_g, const float* __restrict__ bb_g,
    const float* __restrict__ fw, const float* __restrict__ fb,
    const float* __restrict__ clsw, const float* __restrict__ clsb,
    float* __restrict__ out)
{
    __shared__ float tile[2][3][10][10];
    __shared__ float wsm[2][64][28];
    __shared__ float red[512];
    __shared__ float warpred[16][4];
    __shared__ float sfw[64];

    const int b = blockIdx.x;
    const int tid = threadIdx.x;

    for (int t = tid; t < 64 * 27; t += 512) {
        int co_ = t / 27, i_ = t % 27;
        wsm[0][co_][i_] = cw_d[t];
        wsm[1][co_][i_] = cw_g[t];
    }
    for (int t = tid; t < 600; t += 512) {
        int br = t / 300, rem = t % 300;
        int c = rem / 100, yy = (rem % 100) / 10, xx = rem % 10;
        float v = 0.0f;
        if (yy >= 1 && yy <= 8 && xx >= 1 && xx <= 8) {
            const float* src = br ? g_grad : g_dct;
            v = src[(b * 3 + c) * 64 + (yy - 1) * 8 + (xx - 1)];
        }
        tile[br][c][yy][xx] = v;
    }
    __syncthreads();

    const int co = tid >> 3;
    const int oy = tid & 7;

    const float rs = rsqrtf(1.0f + 1e-5f);
    const float kd  = bg_d[co] * rs;
    const float bd  = cb_d[co] * kd + bb_d[co];
    const float kg  = bg_g[co] * rs;
    const float bgc = cb_g[co] * kg + bb_g[co];

    float dv[8], gv[8];
    {
        const float* wr = &wsm[0][co][0];
#pragma unroll
        for (int i = 0; i < 8; i++) {
            float a = 0.0f;
#pragma unroll
            for (int ci = 0; ci < 3; ci++)
#pragma unroll
                for (int ky = 0; ky < 3; ky++)
#pragma unroll
                    for (int kx = 0; kx < 3; kx++)
                        a = fmaf(tile[0][ci][oy + ky][i + kx], wr[ci * 9 + ky * 3 + kx], a);
            dv[i] = fmaxf(fmaf(a, kd, bd), 0.0f);
        }
    }
    {
        const float* wr = &wsm[1][co][0];
#pragma unroll
        for (int i = 0; i < 8; i++) {
            float a = 0.0f;
#pragma unroll
            for (int ci = 0; ci < 3; ci++)
#pragma unroll
                for (int ky = 0; ky < 3; ky++)
#pragma unroll
                    for (int kx = 0; kx < 3; kx++)
                        a = fmaf(tile[1][ci][oy + ky][i + kx], wr[ci * 9 + ky * 3 + kx], a);
            gv[i] = fmaxf(fmaf(a, kg, bgc), 0.0f);
        }
    }

    float psum = 0.0f;
#pragma unroll
    for (int i = 0; i < 8; i++) psum += dv[i] + gv[i];
    red[tid] = psum;

    float aD0, aD1, aG0, aG1;
    {
        const float4* __restrict__ c0 = reinterpret_cast<const float4*>(clsw) + tid * 2;
        const float4* __restrict__ c1 = reinterpret_cast<const float4*>(clsw + 4096) + tid * 2;
        float4 w00 = c0[0], w01 = c0[1];
        float4 w10 = c1[0], w11 = c1[1];
        aD0 = dv[0]*w00.x + dv[1]*w00.y + dv[2]*w00.z + dv[3]*w00.w
            + dv[4]*w01.x + dv[5]*w01.y + dv[6]*w01.z + dv[7]*w01.w;
        aD1 = dv[0]*w10.x + dv[1]*w10.y + dv[2]*w10.z + dv[3]*w10.w
            + dv[4]*w11.x + dv[5]*w11.y + dv[6]*w11.z + dv[7]*w11.w;
        aG0 = gv[0]*w00.x + gv[1]*w00.y + gv[2]*w00.z + gv[3]*w00.w
            + gv[4]*w01.x + gv[5]*w01.y + gv[6]*w01.z + gv[7]*w01.w;
        aG1 = gv[0]*w10.x + gv[1]*w10.y + gv[2]*w10.z + gv[3]*w10.w
            + gv[4]*w11.x + gv[5]*w11.y + gv[6]*w11.z + gv[7]*w11.w;
    }
#pragma unroll
    for (int off = 16; off > 0; off >>= 1) {
        aD0 += __shfl_down_sync(0xffffffffu, aD0, off);
        aD1 += __shfl_down_sync(0xffffffffu, aD1, off);
        aG0 += __shfl_down_sync(0xffffffffu, aG0, off);
        aG1 += __shfl_down_sync(0xffffffffu, aG1, off);
    }
    if ((tid & 31) == 0) {
        warpred[tid >> 5][0] = aD0;
        warpred[tid >> 5][1] = aD1;
        warpred[tid >> 5][2] = aG0;
        warpred[tid >> 5][3] = aG1;
    }
    __syncthreads();

    if (tid < 64) {
        float s = 0.0f;
#pragma unroll
        for (int k = 0; k < 8; k++) s += red[tid * 8 + k];
        sfw[tid] = (s * (1.0f / 64.0f)) * fw[tid];
    }
    __syncthreads();

    if (tid == 0) {
        float tot = fb[0];
#pragma unroll
        for (int c2 = 0; c2 < 64; c2++) tot += sfw[c2];
        float w = 1.0f / (1.0f + expf(-tot));
        float D0 = 0.f, D1 = 0.f, G0 = 0.f, G1 = 0.f;
#pragma unroll
        for (int wd = 0; wd < 16; wd++) {
            D0 += warpred[wd][0];
            D1 += warpred[wd][1];
            G0 += warpred[wd][2];
            G1 += warpred[wd][3];
        }
        out[b * 2 + 0] = w * D0 + (1.0f - w) * G0 + clsb[0];
        out[b * 2 + 1] = w * D1 + (1.0f - w) * G1 + clsb[1];
    }
}

// ---------------------------------------------------------------------------
extern "C" void kernel_launch(void* const* d_in, const int* in_sizes, int n_in,
                              void* d_out, int out_size) {
    const float* x     = (const float*)d_in[0];
    const float* cw_d  = (const float*)d_in[1];
    const float* cb_d  = (const float*)d_in[2];
    const float* bg_d  = (const float*)d_in[3];
    const float* bb_d  = (const float*)d_in[4];
    const float* cw_g  = (const float*)d_in[5];
    const float* cb_g  = (const float*)d_in[6];
    const float* bg_g  = (const float*)d_in[7];
    const float* bb_g  = (const float*)d_in[8];
    const float* fw    = (const float*)d_in[9];
    const float* fb    = (const float*)d_in[10];
    const float* clsw  = (const float*)d_in[11];
    const float* clsb  = (const float*)d_in[12];
    float* out = (float*)d_out;

    setupA_kernel<<<8, 256>>>();
    dct_grad_kernel<<<384, 256>>>(x);
    head_kernel<<<128, 512>>>(cw_d, cb_d, bg_d, bb_d,
                              cw_g, cb_g, bg_g, bb_g,
                              fw, fb, clsw, clsb, out);
}

// round 16
// speedup vs baseline: 1.8384x; 1.0755x over previous
#include <cuda_runtime.h>
#include <math.h>

// Scratch (allocation-free rule: __device__ globals)
__device__ float g_dct[128 * 3 * 64];   // dct branch input, (b,c,8,8)
__device__ float g_grad[128 * 3 * 64];  // grad branch input, (b,c,8,8)

// ---------------------------------------------------------------------------
// Kernel 1: R15 core (MLP-8 batched pass 1) + inline A computation.
// grid = 384, block = 256 (4 teams x 64 threads)
// ---------------------------------------------------------------------------
__global__ void __launch_bounds__(256) dct_grad_kernel(const float* __restrict__ x) {
    __shared__ float Rf2[8][25];
    __shared__ float As[256][8];       // As[m][o] = A[o][m]   (8 KB)
    __shared__ float Tp[4][8][256];    // team partials, later aliased as Ts (32 KB)

    const int tid = threadIdx.x;
    const int blk = blockIdx.x;
    const float* __restrict__ xc = x + (size_t)blk * 65536;

    // --- inline A computation (Chebyshev; ~2 cospif + short FMA chain) --
    if (tid < 200) {
        const int o = tid / 25, k = tid % 25;
        float sk = (k == 0) ? sqrtf(1.0f / 256.0f) : sqrtf(2.0f / 256.0f);
        float si = sqrtf(2.0f / 256.0f);
        float tw = (float)(2 * k + 1) * (1.0f / 512.0f);   // exact
        float c0 = cospif(tw * (float)(32 * o + 15));
        float c1 = cospif(tw * (float)(32 * o + 16));
        Rf2[o][k] = 0.5f * si * sk * (c0 + c1);
    }
    __syncthreads();
    {
        const float th = (float)(2 * tid + 1) * (1.0f / 512.0f);  // exact
        float cp = cospif(th);
        const float twoc = 2.0f * cp;
        float cpp = 1.0f;
        float a[8];
#pragma unroll
        for (int o = 0; o < 8; o++) a[o] = fmaf(Rf2[o][1], cp, Rf2[o][0]);
#pragma unroll
        for (int k = 2; k < 25; k++) {
            float ck = fmaf(twoc, cp, -cpp);
#pragma unroll
            for (int o = 0; o < 8; o++) a[o] = fmaf(Rf2[o][k], ck, a[o]);
            cpp = cp; cp = ck;
        }
#pragma unroll
        for (int o = 0; o < 8; o++) As[tid][o] = a[o];
    }
    __syncthreads();

    const int team = tid >> 6;         // rows 64*team .. 64*team+63
    const int t64  = tid & 63;         // columns 4*t64 .. 4*t64+3

    float acc[8][4];
#pragma unroll
    for (int o = 0; o < 8; o++)
#pragma unroll
        for (int c = 0; c < 4; c++) acc[o][c] = 0.0f;

    const float4* __restrict__ xrow = reinterpret_cast<const float4*>(xc) + t64;
    const int mbase = team * 64;

#pragma unroll
    for (int chunk = 0; chunk < 8; chunk++) {
        // batch 8 LDG.128 back-to-back -> MLP 8 per thread
        float4 xv[8];
#pragma unroll
        for (int u = 0; u < 8; u++)
            xv[u] = xrow[(size_t)(mbase + chunk * 8 + u) * 64];
#pragma unroll
        for (int u = 0; u < 8; u++) {
            const int m = mbase + chunk * 8 + u;
            float4 a0 = *reinterpret_cast<const float4*>(&As[m][0]);
            float4 a1 = *reinterpret_cast<const float4*>(&As[m][4]);
            acc[0][0] = fmaf(a0.x, xv[u].x, acc[0][0]);
            acc[0][1] = fmaf(a0.x, xv[u].y, acc[0][1]);
            acc[0][2] = fmaf(a0.x, xv[u].z, acc[0][2]);
            acc[0][3] = fmaf(a0.x, xv[u].w, acc[0][3]);
            acc[1][0] = fmaf(a0.y, xv[u].x, acc[1][0]);
            acc[1][1] = fmaf(a0.y, xv[u].y, acc[1][1]);
            acc[1][2] = fmaf(a0.y, xv[u].z, acc[1][2]);
            acc[1][3] = fmaf(a0.y, xv[u].w, acc[1][3]);
            acc[2][0] = fmaf(a0.z, xv[u].x, acc[2][0]);
            acc[2][1] = fmaf(a0.z, xv[u].y, acc[2][1]);
            acc[2][2] = fmaf(a0.z, xv[u].z, acc[2][2]);
            acc[2][3] = fmaf(a0.z, xv[u].w, acc[2][3]);
            acc[3][0] = fmaf(a0.w, xv[u].x, acc[3][0]);
            acc[3][1] = fmaf(a0.w, xv[u].y, acc[3][1]);
            acc[3][2] = fmaf(a0.w, xv[u].z, acc[3][2]);
            acc[3][3] = fmaf(a0.w, xv[u].w, acc[3][3]);
            acc[4][0] = fmaf(a1.x, xv[u].x, acc[4][0]);
            acc[4][1] = fmaf(a1.x, xv[u].y, acc[4][1]);
            acc[4][2] = fmaf(a1.x, xv[u].z, acc[4][2]);
            acc[4][3] = fmaf(a1.x, xv[u].w, acc[4][3]);
            acc[5][0] = fmaf(a1.y, xv[u].x, acc[5][0]);
            acc[5][1] = fmaf(a1.y, xv[u].y, acc[5][1]);
            acc[5][2] = fmaf(a1.y, xv[u].z, acc[5][2]);
            acc[5][3] = fmaf(a1.y, xv[u].w, acc[5][3]);
            acc[6][0] = fmaf(a1.z, xv[u].x, acc[6][0]);
            acc[6][1] = fmaf(a1.z, xv[u].y, acc[6][1]);
            acc[6][2] = fmaf(a1.z, xv[u].z, acc[6][2]);
            acc[6][3] = fmaf(a1.z, xv[u].w, acc[6][3]);
            acc[7][0] = fmaf(a1.w, xv[u].x, acc[7][0]);
            acc[7][1] = fmaf(a1.w, xv[u].y, acc[7][1]);
            acc[7][2] = fmaf(a1.w, xv[u].z, acc[7][2]);
            acc[7][3] = fmaf(a1.w, xv[u].w, acc[7][3]);
        }
    }
#pragma unroll
    for (int o = 0; o < 8; o++)
        *reinterpret_cast<float4*>(&Tp[team][o][t64 * 4]) =
            make_float4(acc[o][0], acc[o][1], acc[o][2], acc[o][3]);
    __syncthreads();

    float* TsF = &Tp[0][0][0];   // Ts[o][c] = TsF[o*256 + c]
    {
        float s[8];
#pragma unroll
        for (int o = 0; o < 8; o++)
            s[o] = Tp[0][o][tid] + Tp[1][o][tid] + Tp[2][o][tid] + Tp[3][o][tid];
#pragma unroll
        for (int o = 0; o < 8; o++) TsF[o * 256 + tid] = s[o];
    }
    __syncthreads();

    if (tid < 64) {
        const int oy = tid >> 3, ox = tid & 7;
        const float* tsr = TsF + oy * 256;
        float s = 0.0f;
#pragma unroll 8
        for (int j = 0; j < 256; j++)
            s = fmaf(tsr[j], As[j][ox], s);
        g_dct[blk * 64 + tid] = s;
    } else if (tid < 128) {
        const int cl = tid - 64;
        const int r = 32 * (cl >> 3) + 15;
        const int c = 32 * (cl & 7) + 15;
        float p[4][4];
#pragma unroll
        for (int a = 0; a < 4; a++)
#pragma unroll
            for (int b = 0; b < 4; b++)
                p[a][b] = xc[(r - 1 + a) * 256 + (c - 1 + b)];
        float gsum = 0.0f;
#pragma unroll
        for (int i = 0; i < 2; i++)
#pragma unroll
            for (int j = 0; j < 2; j++) {
                float gx = (p[i][j + 2] - p[i][j])
                         + 2.0f * (p[i + 1][j + 2] - p[i + 1][j])
                         + (p[i + 2][j + 2] - p[i + 2][j]);
                float gy = (p[i + 2][j] - p[i][j])
                         + 2.0f * (p[i + 2][j + 1] - p[i][j + 1])
                         + (p[i + 2][j + 2] - p[i][j + 2]);
                gsum += sqrtf(gx * gx + gy * gy);
            }
        g_grad[blk * 64 + cl] = 0.25f * gsum;
    }
}

// ---------------------------------------------------------------------------
// Kernel 2 (R7 head, verbatim): grid = 128, block = 512.
// ---------------------------------------------------------------------------
__global__ void __launch_bounds__(512) head_kernel(
    const float* __restrict__ cw_d, const float* __restrict__ cb_d,
    const float* __restrict__ bg_d, const float* __restrict__ bb_d,
    const float* __restrict__ cw_g, const float* __restrict__ cb_g,
    const float* __restrict__ bg_g, const float* __restrict__ bb_g,
    const float* __restrict__ fw, const float* __restrict__ fb,
    const float* __restrict__ clsw, const float* __restrict__ clsb,
    float* __restrict__ out)
{
    __shared__ float tile[2][3][10][10];
    __shared__ float wsm[2][64][28];
    __shared__ float red[512];
    __shared__ float warpred[16][4];
    __shared__ float sfw[64];

    const int b = blockIdx.x;
    const int tid = threadIdx.x;

    for (int t = tid; t < 64 * 27; t += 512) {
        int co_ = t / 27, i_ = t % 27;
        wsm[0][co_][i_] = cw_d[t];
        wsm[1][co_][i_] = cw_g[t];
    }
    for (int t = tid; t < 600; t += 512) {
        int br = t / 300, rem = t % 300;
        int c = rem / 100, yy = (rem % 100) / 10, xx = rem % 10;
        float v = 0.0f;
        if (yy >= 1 && yy <= 8 && xx >= 1 && xx <= 8) {
            const float* src = br ? g_grad : g_dct;
            v = src[(b * 3 + c) * 64 + (yy - 1) * 8 + (xx - 1)];
        }
        tile[br][c][yy][xx] = v;
    }
    __syncthreads();

    const int co = tid >> 3;
    const int oy = tid & 7;

    const float rs = rsqrtf(1.0f + 1e-5f);
    const float kd  = bg_d[co] * rs;
    const float bd  = cb_d[co] * kd + bb_d[co];
    const float kg  = bg_g[co] * rs;
    const float bgc = cb_g[co] * kg + bb_g[co];

    float dv[8], gv[8];
    {
        const float* wr = &wsm[0][co][0];
#pragma unroll
        for (int i = 0; i < 8; i++) {
            float a = 0.0f;
#pragma unroll
            for (int ci = 0; ci < 3; ci++)
#pragma unroll
                for (int ky = 0; ky < 3; ky++)
#pragma unroll
                    for (int kx = 0; kx < 3; kx++)
                        a = fmaf(tile[0][ci][oy + ky][i + kx], wr[ci * 9 + ky * 3 + kx], a);
            dv[i] = fmaxf(fmaf(a, kd, bd), 0.0f);
        }
    }
    {
        const float* wr = &wsm[1][co][0];
#pragma unroll
        for (int i = 0; i < 8; i++) {
            float a = 0.0f;
#pragma unroll
            for (int ci = 0; ci < 3; ci++)
#pragma unroll
                for (int ky = 0; ky < 3; ky++)
#pragma unroll
                    for (int kx = 0; kx < 3; kx++)
                        a = fmaf(tile[1][ci][oy + ky][i + kx], wr[ci * 9 + ky * 3 + kx], a);
            gv[i] = fmaxf(fmaf(a, kg, bgc), 0.0f);
        }
    }

    float psum = 0.0f;
#pragma unroll
    for (int i = 0; i < 8; i++) psum += dv[i] + gv[i];
    red[tid] = psum;

    float aD0, aD1, aG0, aG1;
    {
        const float4* __restrict__ c0 = reinterpret_cast<const float4*>(clsw) + tid * 2;
        const float4* __restrict__ c1 = reinterpret_cast<const float4*>(clsw + 4096) + tid * 2;
        float4 w00 = c0[0], w01 = c0[1];
        float4 w10 = c1[0], w11 = c1[1];
        aD0 = dv[0]*w00.x + dv[1]*w00.y + dv[2]*w00.z + dv[3]*w00.w
            + dv[4]*w01.x + dv[5]*w01.y + dv[6]*w01.z + dv[7]*w01.w;
        aD1 = dv[0]*w10.x + dv[1]*w10.y + dv[2]*w10.z + dv[3]*w10.w
            + dv[4]*w11.x + dv[5]*w11.y + dv[6]*w11.z + dv[7]*w11.w;
        aG0 = gv[0]*w00.x + gv[1]*w00.y + gv[2]*w00.z + gv[3]*w00.w
            + gv[4]*w01.x + gv[5]*w01.y + gv[6]*w01.z + gv[7]*w01.w;
        aG1 = gv[0]*w10.x + gv[1]*w10.y + gv[2]*w10.z + gv[3]*w10.w
            + gv[4]*w11.x + gv[5]*w11.y + gv[6]*w11.z + gv[7]*w11.w;
    }
#pragma unroll
    for (int off = 16; off > 0; off >>= 1) {
        aD0 += __shfl_down_sync(0xffffffffu, aD0, off);
        aD1 += __shfl_down_sync(0xffffffffu, aD1, off);
        aG0 += __shfl_down_sync(0xffffffffu, aG0, off);
        aG1 += __shfl_down_sync(0xffffffffu, aG1, off);
    }
    if ((tid & 31) == 0) {
        warpred[tid >> 5][0] = aD0;
        warpred[tid >> 5][1] = aD1;
        warpred[tid >> 5][2] = aG0;
        warpred[tid >> 5][3] = aG1;
    }
    __syncthreads();

    if (tid < 64) {
        float s = 0.0f;
#pragma unroll
        for (int k = 0; k < 8; k++) s += red[tid * 8 + k];
        sfw[tid] = (s * (1.0f / 64.0f)) * fw[tid];
    }
    __syncthreads();

    if (tid == 0) {
        float tot = fb[0];
#pragma unroll
        for (int c2 = 0; c2 < 64; c2++) tot += sfw[c2];
        float w = 1.0f / (1.0f + expf(-tot));
        float D0 = 0.f, D1 = 0.f, G0 = 0.f, G1 = 0.f;
#pragma unroll
        for (int wd = 0; wd < 16; wd++) {
            D0 += warpred[wd][0];
            D1 += warpred[wd][1];
            G0 += warpred[wd][2];
            G1 += warpred[wd][3];
        }
        out[b * 2 + 0] = w * D0 + (1.0f - w) * G0 + clsb[0];
        out[b * 2 + 1] = w * D1 + (1.0f - w) * G1 + clsb[1];
    }
}

// ---------------------------------------------------------------------------
extern "C" void kernel_launch(void* const* d_in, const int* in_sizes, int n_in,
                              void* d_out, int out_size) {
    const float* x     = (const float*)d_in[0];
    const float* cw_d  = (const float*)d_in[1];
    const float* cb_d  = (const float*)d_in[2];
    const float* bg_d  = (const float*)d_in[3];
    const float* bb_d  = (const float*)d_in[4];
    const float* cw_g  = (const float*)d_in[5];
    const float* cb_g  = (const float*)d_in[6];
    const float* bg_g  = (const float*)d_in[7];
    const float* bb_g  = (const float*)d_in[8];
    const float* fw    = (const float*)d_in[9];
    const float* fb    = (const float*)d_in[10];
    const float* clsw  = (const float*)d_in[11];
    const float* clsb  = (const float*)d_in[12];
    float* out = (float*)d_out;

    dct_grad_kernel<<<384, 256>>>(x);
    head_kernel<<<128, 512>>>(cw_d, cb_d, bg_d, bb_d,
                              cw_g, cb_g, bg_g, bb_g,
                              fw, fb, clsw, clsb, out);
}